// round 14
// baseline (speedup 1.0000x reference)
#include <cuda_runtime.h>
#include <cstdint>

// ===========================================================================
// SelfAttention via mma.sync tf32 — Round 14: flash tile-level software
// pipeline — PV(kt) interleaved with S(kt+1) (independent mma chains) with
// double-buffered K/V; 256 thr / 256 q-rows / 1 CTA/SM. GEMM = R13 best.
//   K1: mma_gemm   x @ w_qkv            -> g_qkv  [16384 x 768]
//   K2: mma_flash  attention            -> g_attn [16384 x 256]
//   K1: mma_gemm   g_attn @ w_out + b   -> out    [16384 x 512]
// ===========================================================================

#define NTOK   16384
#define DMODEL 512
#define INNER  256
#define QKVN   768
#define HEADS  4
#define DH     64
#define TSEQ   2048

__device__ float g_qkv[NTOK * QKVN];    // 48 MB
__device__ float g_attn[NTOK * INNER];  // 16 MB

__device__ __forceinline__ uint32_t smem_u32(const void* p) {
    uint32_t a;
    asm("{ .reg .u64 t; cvta.to.shared.u64 t, %1; cvt.u32.u64 %0, t; }"
        : "=r"(a) : "l"(p));
    return a;
}
__device__ __forceinline__ uint32_t f2tf32(float x) {
    uint32_t r;
    asm("cvt.rna.tf32.f32 %0, %1;" : "=r"(r) : "f"(x));
    return r;
}
__device__ __forceinline__ uint32_t tf32_w(uint32_t bits) {
    return f2tf32(__uint_as_float(bits));
}
__device__ __forceinline__ float ex2f(float x) {
    float r;
    asm("ex2.approx.f32 %0, %1;" : "=f"(r) : "f"(x));
    return r;
}
__device__ __forceinline__ void cp_async16(uint32_t saddr, const void* gptr) {
    asm volatile("cp.async.ca.shared.global [%0], [%1], 16;"
                 :: "r"(saddr), "l"(gptr));
}
#define CP_COMMIT() asm volatile("cp.async.commit_group;" ::: "memory")
#define CP_WAIT0()  asm volatile("cp.async.wait_group 0;" ::: "memory")

__device__ __forceinline__ void ldsm_x4(uint32_t& r0, uint32_t& r1,
                                        uint32_t& r2, uint32_t& r3,
                                        uint32_t saddr) {
    asm volatile("ldmatrix.sync.aligned.m8n8.x4.shared.b16 {%0,%1,%2,%3}, [%4];"
                 : "=r"(r0), "=r"(r1), "=r"(r2), "=r"(r3) : "r"(saddr));
}

__device__ __forceinline__ void mma_tf32(float* c, const uint32_t* a,
                                         uint32_t b0, uint32_t b1) {
    asm volatile(
        "mma.sync.aligned.m16n8k8.row.col.f32.tf32.tf32.f32 "
        "{%0,%1,%2,%3}, {%4,%5,%6,%7}, {%8,%9}, {%0,%1,%2,%3};"
        : "+f"(c[0]), "+f"(c[1]), "+f"(c[2]), "+f"(c[3])
        : "r"(a[0]), "r"(a[1]), "r"(a[2]), "r"(a[3]), "r"(b0), "r"(b1));
}

// ---------------------------------------------------------------------------
// GEMM (R13 best): 256 thr, CTA 256x128, kchunk 32, warp tile 64x64,
// cp.async double buffer, A-frags via LDSM.x4, cvt at fragment load.
// ---------------------------------------------------------------------------
#define AP 36
#define BP 136
#define GM_BS    (256 * AP)
#define GM_WORDS (GM_BS + 32 * BP)
#define GM_BYTES (2 * GM_WORDS * 4)      // 108544 B

__global__ __launch_bounds__(256, 1) void mma_gemm_kernel(
    const float* __restrict__ A, const float* __restrict__ B,
    const float* __restrict__ bias, float* __restrict__ C,
    int M, int N, int K)
{
    extern __shared__ uint32_t sm[];
    const uint32_t smb = smem_u32(sm);

    const int tid = threadIdx.x;
    const int wid = tid >> 5, lane = tid & 31;
    const int g = lane >> 2, tg = lane & 3;
    const int wm = wid & 3, wn = wid >> 2;
    const int row0 = blockIdx.y * 256, col0 = blockIdx.x * 128;

    const int lmat = lane >> 3, lrow = lane & 7;
    const int afix = ((lmat & 1) * 8 + lrow) * AP + (lmat >> 1) * 4;

    int ar[8], ac[8], br[4], bc[4];
    #pragma unroll
    for (int i = 0; i < 8; i++) {
        int flat = tid * 4 + i * 1024;
        ar[i] = flat >> 5; ac[i] = flat & 31;
    }
    #pragma unroll
    for (int i = 0; i < 4; i++) {
        int flat = tid * 4 + i * 1024;
        br[i] = flat >> 7; bc[i] = flat & 127;
    }

    float c[4][8][4];
    #pragma unroll
    for (int mt = 0; mt < 4; mt++)
        #pragma unroll
        for (int nt = 0; nt < 8; nt++)
            #pragma unroll
            for (int j = 0; j < 4; j++) c[mt][nt][j] = 0.f;

    const int nchunks = K >> 5;

    #pragma unroll
    for (int i = 0; i < 8; i++)
        cp_async16(smb + (ar[i] * AP + ac[i]) * 4,
                   A + (size_t)(row0 + ar[i]) * K + ac[i]);
    #pragma unroll
    for (int i = 0; i < 4; i++)
        cp_async16(smb + (GM_BS + br[i] * BP + bc[i]) * 4,
                   B + (size_t)br[i] * N + col0 + bc[i]);
    CP_COMMIT();
    CP_WAIT0();
    __syncthreads();

    for (int ch = 0; ch < nchunks; ch++) {
        const int cur = ch & 1;
        const uint32_t sA = smb + cur * GM_WORDS * 4;
        const uint32_t* Bs = sm + cur * GM_WORDS + GM_BS;

        if (ch + 1 < nchunks) {
            const int nxt = cur ^ 1;
            const uint32_t nb = smb + nxt * GM_WORDS * 4;
            int k0 = (ch + 1) * 32;
            #pragma unroll
            for (int i = 0; i < 8; i++)
                cp_async16(nb + (ar[i] * AP + ac[i]) * 4,
                           A + (size_t)(row0 + ar[i]) * K + k0 + ac[i]);
            #pragma unroll
            for (int i = 0; i < 4; i++)
                cp_async16(nb + (GM_BS + br[i] * BP + bc[i]) * 4,
                           B + (size_t)(k0 + br[i]) * N + col0 + bc[i]);
            CP_COMMIT();
        }

        #pragma unroll
        for (int ks = 0; ks < 4; ks++) {
            uint32_t a[4][4], b[8][2];
            #pragma unroll
            for (int mt = 0; mt < 4; mt++) {
                uint32_t addr = sA + (((wm * 64 + mt * 16) * AP) + ks * 8 + afix) * 4;
                ldsm_x4(a[mt][0], a[mt][1], a[mt][2], a[mt][3], addr);
                a[mt][0] = tf32_w(a[mt][0]);
                a[mt][1] = tf32_w(a[mt][1]);
                a[mt][2] = tf32_w(a[mt][2]);
                a[mt][3] = tf32_w(a[mt][3]);
            }
            #pragma unroll
            for (int nt = 0; nt < 8; nt++) {
                int bb = (ks * 8 + tg) * BP + wn * 64 + nt * 8 + g;
                b[nt][0] = tf32_w(Bs[bb]);
                b[nt][1] = tf32_w(Bs[bb + 4 * BP]);
            }
            #pragma unroll
            for (int mt = 0; mt < 4; mt++)
                #pragma unroll
                for (int nt = 0; nt < 8; nt++)
                    mma_tf32(c[mt][nt], a[mt], b[nt][0], b[nt][1]);
        }

        if (ch + 1 < nchunks) {
            CP_WAIT0();
            __syncthreads();
        }
    }

    #pragma unroll
    for (int mt = 0; mt < 4; mt++) {
        int r = row0 + wm * 64 + mt * 16 + g;
        #pragma unroll
        for (int nt = 0; nt < 8; nt++) {
            int cc = col0 + wn * 64 + nt * 8 + 2 * tg;
            float bx = 0.f, by = 0.f;
            if (bias) { bx = bias[cc]; by = bias[cc + 1]; }
            float2 v0 = make_float2(c[mt][nt][0] + bx, c[mt][nt][1] + by);
            float2 v1 = make_float2(c[mt][nt][2] + bx, c[mt][nt][3] + by);
            *reinterpret_cast<float2*>(C + (size_t)r * N + cc) = v0;
            *reinterpret_cast<float2*>(C + (size_t)(r + 8) * N + cc) = v1;
        }
    }
}

// ---------------------------------------------------------------------------
// Flash attention, flat softmax, tile software-pipeline:
//   per kt: fill KV(kt+1) -> softmax(kt)/P -> interleaved [PV(kt) || S(kt+1)]
// 256 thr / 8 warps / 256 q-rows per CTA, 1 CTA/SM. kv tiles 64, K/V double
// buffered. Warp owns 32 q-rows = 2 mtiles; K/V b-frags shared across mtiles;
// Q frags register-resident (LDSM); K b-frags + P a-frags via LDSM.x4;
// exp = ex2.approx with log2e folded into the Q scale.
// Pitches: Qs/Ks/Ps 68 (==4 mod 32), Vs 72 (==8). smem = 210944 B.
// ---------------------------------------------------------------------------
#define QP 68
#define VP 72
#define PP 68
#define FA_K     (256 * QP)                  // Q: 256 x 68
#define KBUF     (64 * QP)
#define FA_V     (FA_K + 2 * KBUF)           // K: 2 x 64 x 68
#define VBUF     (64 * VP)
#define FA_P     (FA_V + 2 * VBUF)           // V: 2 x 64 x 72
#define FA_WORDS (FA_P + 256 * PP)           // P: 256 x 68
#define FA_BYTES (FA_WORDS * 4)              // 210944 B

#define QSCALE 0.180336880f   // 0.125 * log2(e)

__global__ __launch_bounds__(256, 1) void mma_flash_kernel(
    const float* __restrict__ qkv, float* __restrict__ attn)
{
    extern __shared__ uint32_t sm[];
    const uint32_t smb = smem_u32(sm);
    uint32_t* Qs = sm;
    uint32_t* Ps = sm + FA_P;
    const uint32_t Ps_b = smb + FA_P * 4;

    const int tid = threadIdx.x;
    const int wid = tid >> 5, lane = tid & 31;
    const int g = lane >> 2, tg = lane & 3;
    const int qt = blockIdx.x, h = blockIdx.y, bb = blockIdx.z;
    const int tok_q0 = bb * TSEQ + qt * 256;
    const int wb0 = wid * 32, wb1 = wid * 32 + 16;

    const int lmat = lane >> 3, lrow = lane & 7;
    const int afixP = ((lmat & 1) * 8 + lrow) * PP + (lmat >> 1) * 4;
    const int bfixK = ((lmat >> 1) * 8 + lrow) * QP + (lmat & 1) * 4;

    // Q tile 256x64, pre-scaled by 0.125*log2e
    #pragma unroll
    for (int i = 0; i < 16; i++) {
        int flat = tid * 4 + i * 1024;
        int r = flat >> 6, cc = flat & 63;
        float4 v = *reinterpret_cast<const float4*>(
            qkv + (size_t)(tok_q0 + r) * QKVN + h * DH + cc);
        uint4 w;
        w.x = f2tf32(v.x * QSCALE);
        w.y = f2tf32(v.y * QSCALE);
        w.z = f2tf32(v.z * QSCALE);
        w.w = f2tf32(v.w * QSCALE);
        *reinterpret_cast<uint4*>(&Qs[r * QP + cc]) = w;
    }
    __syncthreads();

    // hoist Q fragments to registers via LDSM
    uint32_t qa[2][8][4];
    #pragma unroll
    for (int ks = 0; ks < 8; ks++) {
        ldsm_x4(qa[0][ks][0], qa[0][ks][1], qa[0][ks][2], qa[0][ks][3],
                smb + (wb0 * QP + ks * 8 + afixP) * 4);
        ldsm_x4(qa[1][ks][0], qa[1][ks][1], qa[1][ks][2], qa[1][ks][3],
                smb + (wb1 * QP + ks * 8 + afixP) * 4);
    }

    float ps[2][2] = {{0.f, 0.f}, {0.f, 0.f}};
    float o[2][8][4];
    #pragma unroll
    for (int mt = 0; mt < 2; mt++)
        #pragma unroll
        for (int nt = 0; nt < 8; nt++)
            #pragma unroll
            for (int j = 0; j < 4; j++) o[mt][nt][j] = 0.f;

    // ---- fill helper (sync LDG+cvt+STS.128), 64x64 K and V tiles ----
    auto fill_kv = [&](int kt, int buf) {
        const int tok_k0 = bb * TSEQ + kt * 64;
        uint32_t* Kb = sm + FA_K + buf * KBUF;
        uint32_t* Vb = sm + FA_V + buf * VBUF;
        #pragma unroll
        for (int i = 0; i < 4; i++) {
            int flat = tid * 4 + i * 1024;
            int r = flat >> 6, cc = flat & 63;
            size_t base = (size_t)(tok_k0 + r) * QKVN + h * DH + cc;
            float4 kv4 = *reinterpret_cast<const float4*>(qkv + base + INNER);
            float4 vv4 = *reinterpret_cast<const float4*>(qkv + base + 2 * INNER);
            uint4 kw, vw;
            kw.x = f2tf32(kv4.x); kw.y = f2tf32(kv4.y);
            kw.z = f2tf32(kv4.z); kw.w = f2tf32(kv4.w);
            vw.x = f2tf32(vv4.x); vw.y = f2tf32(vv4.y);
            vw.z = f2tf32(vv4.z); vw.w = f2tf32(vv4.w);
            *reinterpret_cast<uint4*>(&Kb[r * QP + cc]) = kw;
            *reinterpret_cast<uint4*>(&Vb[r * VP + cc]) = vw;
        }
    };

    // ---- S-compute helper: s(kb from K buffer buf) ----
    auto s_tile = [&](float (*t0)[4], float (*t1)[4], int buf) {
        const uint32_t Kb_b = smb + (FA_K + buf * KBUF) * 4;
        #pragma unroll
        for (int nt = 0; nt < 8; nt++)
            #pragma unroll
            for (int j = 0; j < 4; j++) { t0[nt][j] = 0.f; t1[nt][j] = 0.f; }
        #pragma unroll
        for (int ks = 0; ks < 8; ks++) {
            #pragma unroll
            for (int j = 0; j < 4; j++) {
                uint32_t kb[4];
                ldsm_x4(kb[0], kb[1], kb[2], kb[3],
                        Kb_b + (j * 16 * QP + ks * 8 + bfixK) * 4);
                mma_tf32(t0[2 * j],     qa[0][ks], kb[0], kb[1]);
                mma_tf32(t1[2 * j],     qa[1][ks], kb[0], kb[1]);
                mma_tf32(t0[2 * j + 1], qa[0][ks], kb[2], kb[3]);
                mma_tf32(t1[2 * j + 1], qa[1][ks], kb[2], kb[3]);
            }
        }
    };

    const int NT = TSEQ / 64;
    float s0[8][4], s1[8][4];

    // prologue: KV(0), S(0)
    fill_kv(0, 0);
    __syncthreads();
    s_tile(s0, s1, 0);

    for (int kt = 0; kt < NT; kt++) {
        const int cur = kt & 1;
        __syncthreads();   // S(kt) + PV(kt-1) readers done with buf cur^1
        if (kt + 1 < NT) fill_kv(kt + 1, cur ^ 1);
        __syncthreads();

        // ---- softmax(kt): P = exp2(S), partial row sums
        #pragma unroll
        for (int mt = 0; mt < 2; mt++) {
            float (*s)[4] = mt ? s1 : s0;
            float sum0 = 0.f, sum1 = 0.f;
            #pragma unroll
            for (int nt = 0; nt < 8; nt++) {
                s[nt][0] = ex2f(s[nt][0]);
                s[nt][1] = ex2f(s[nt][1]);
                s[nt][2] = ex2f(s[nt][2]);
                s[nt][3] = ex2f(s[nt][3]);
                sum0 += s[nt][0] + s[nt][1];
                sum1 += s[nt][2] + s[nt][3];
            }
            ps[mt][0] += sum0;
            ps[mt][1] += sum1;
            const int wb = mt ? wb1 : wb0;
            int r0 = (wb + g) * PP, r1 = (wb + g + 8) * PP;
            #pragma unroll
            for (int nt = 0; nt < 8; nt++) {
                int cc = nt * 8 + 2 * tg;
                uint2 p0, p1;
                p0.x = f2tf32(s[nt][0]); p0.y = f2tf32(s[nt][1]);
                p1.x = f2tf32(s[nt][2]); p1.y = f2tf32(s[nt][3]);
                *reinterpret_cast<uint2*>(&Ps[r0 + cc]) = p0;
                *reinterpret_cast<uint2*>(&Ps[r1 + cc]) = p1;
            }
        }
        __syncwarp();

        const uint32_t* Vs = sm + FA_V + cur * VBUF;

        if (kt + 1 < NT) {
            // ---- interleaved: PV(kt) (P, V buf cur) || S(kt+1) (K buf cur^1)
            float sn0[8][4], sn1[8][4];
            const uint32_t Kb_b = smb + (FA_K + (cur ^ 1) * KBUF) * 4;
            #pragma unroll
            for (int nt = 0; nt < 8; nt++)
                #pragma unroll
                for (int j = 0; j < 4; j++) { sn0[nt][j] = 0.f; sn1[nt][j] = 0.f; }
            #pragma unroll
            for (int ks = 0; ks < 8; ks++) {
                // S(kt+1) part
                #pragma unroll
                for (int j = 0; j < 4; j++) {
                    uint32_t kb[4];
                    ldsm_x4(kb[0], kb[1], kb[2], kb[3],
                            Kb_b + (j * 16 * QP + ks * 8 + bfixK) * 4);
                    mma_tf32(sn0[2 * j],     qa[0][ks], kb[0], kb[1]);
                    mma_tf32(sn1[2 * j],     qa[1][ks], kb[0], kb[1]);
                    mma_tf32(sn0[2 * j + 1], qa[0][ks], kb[2], kb[3]);
                    mma_tf32(sn1[2 * j + 1], qa[1][ks], kb[2], kb[3]);
                }
                // PV(kt) part
                uint32_t a0[4], a1[4];
                ldsm_x4(a0[0], a0[1], a0[2], a0[3],
                        Ps_b + (wb0 * PP + ks * 8 + afixP) * 4);
                ldsm_x4(a1[0], a1[1], a1[2], a1[3],
                        Ps_b + (wb1 * PP + ks * 8 + afixP) * 4);
                #pragma unroll
                for (int nt = 0; nt < 8; nt++) {
                    int bidx = (ks * 8 + tg) * VP + nt * 8 + g;
                    uint32_t vb0 = Vs[bidx], vb1 = Vs[bidx + 4 * VP];
                    mma_tf32(o[0][nt], a0, vb0, vb1);
                    mma_tf32(o[1][nt], a1, vb0, vb1);
                }
            }
            // rotate
            #pragma unroll
            for (int nt = 0; nt < 8; nt++)
                #pragma unroll
                for (int j = 0; j < 4; j++) {
                    s0[nt][j] = sn0[nt][j];
                    s1[nt][j] = sn1[nt][j];
                }
        } else {
            // last tile: PV only
            #pragma unroll
            for (int ks = 0; ks < 8; ks++) {
                uint32_t a0[4], a1[4];
                ldsm_x4(a0[0], a0[1], a0[2], a0[3],
                        Ps_b + (wb0 * PP + ks * 8 + afixP) * 4);
                ldsm_x4(a1[0], a1[1], a1[2], a1[3],
                        Ps_b + (wb1 * PP + ks * 8 + afixP) * 4);
                #pragma unroll
                for (int nt = 0; nt < 8; nt++) {
                    int bidx = (ks * 8 + tg) * VP + nt * 8 + g;
                    uint32_t vb0 = Vs[bidx], vb1 = Vs[bidx + 4 * VP];
                    mma_tf32(o[0][nt], a0, vb0, vb1);
                    mma_tf32(o[1][nt], a1, vb0, vb1);
                }
            }
        }
        __syncwarp();
    }

    // final row-sum reduction + normalize + store
    #pragma unroll
    for (int mt = 0; mt < 2; mt++) {
        float l0 = ps[mt][0], l1 = ps[mt][1];
        l0 += __shfl_xor_sync(0xffffffffu, l0, 1);
        l0 += __shfl_xor_sync(0xffffffffu, l0, 2);
        l1 += __shfl_xor_sync(0xffffffffu, l1, 1);
        l1 += __shfl_xor_sync(0xffffffffu, l1, 2);
        const float li0 = 1.f / l0, li1 = 1.f / l1;
        const int r = tok_q0 + wid * 32 + mt * 16 + g;
        #pragma unroll
        for (int nt = 0; nt < 8; nt++) {
            int cc = h * DH + nt * 8 + 2 * tg;
            float2 v0 = make_float2(o[mt][nt][0] * li0, o[mt][nt][1] * li0);
            float2 v1 = make_float2(o[mt][nt][2] * li1, o[mt][nt][3] * li1);
            *reinterpret_cast<float2*>(attn + (size_t)r * INNER + cc) = v0;
            *reinterpret_cast<float2*>(attn + (size_t)(r + 8) * INNER + cc) = v1;
        }
    }
}

// ---------------------------------------------------------------------------
extern "C" void kernel_launch(void* const* d_in, const int* in_sizes, int n_in,
                              void* d_out, int out_size)
{
    (void)in_sizes; (void)n_in; (void)out_size;
    const float* x     = (const float*)d_in[0];
    const float* w_qkv = (const float*)d_in[1];
    const float* w_out = (const float*)d_in[2];
    const float* b_out = (const float*)d_in[3];
    float* out = (float*)d_out;

    float *qkv_p, *attn_p;
    cudaGetSymbolAddress((void**)&qkv_p,  g_qkv);
    cudaGetSymbolAddress((void**)&attn_p, g_attn);

    cudaFuncSetAttribute(mma_gemm_kernel,
        cudaFuncAttributeMaxDynamicSharedMemorySize, GM_BYTES);
    cudaFuncSetAttribute(mma_flash_kernel,
        cudaFuncAttributeMaxDynamicSharedMemorySize, FA_BYTES);

    // QKV projection: [16384,512] @ [512,768]
    mma_gemm_kernel<<<dim3(QKVN / 128, NTOK / 256), 256, GM_BYTES>>>(
        x, w_qkv, nullptr, qkv_p, NTOK, QKVN, DMODEL);
    // attention: 256 q-rows per CTA
    mma_flash_kernel<<<dim3(TSEQ / 256, HEADS, 8), 256, FA_BYTES>>>(
        qkv_p, attn_p);
    // output projection: [16384,256] @ [256,512] + bias
    mma_gemm_kernel<<<dim3(DMODEL / 128, NTOK / 256), 256, GM_BYTES>>>(
        attn_p, w_out, b_out, out, NTOK, DMODEL, INNER);
}